// round 9
// baseline (speedup 1.0000x reference)
#include <cuda_runtime.h>
#include <cuda_fp16.h>

#define IN_F   128
#define HEADS  8
#define HC     16   // HEADS * OUT_C
#define NMAX   100000
#define EMAX   3200000
#define NT     256   // threads (=nodes) per CTA in node_kernel
#define KT     32    // k-tile width
#define XPAD   36    // padded row stride (floats)

// Static scratch (no allocations allowed)
__device__ __align__(128) __half2 g_hh[NMAX * 8];     // h in fp16: 32B per node row
__device__ __align__(128) float g_asrc[NMAX * HEADS]; // 32B per node row
__device__ __align__(128) float g_adst[NMAX * HEADS]; // 32B per node row
__device__ int g_cnt[NMAX];      // in-degree
__device__ int g_base[NMAX];     // CSR offsets (exclusive scan)
__device__ int g_cursor[NMAX];   // scatter cursors
__device__ int g_srcs[EMAX];     // src ids grouped by dst
__device__ int g_partial[128];   // per-block scan sums
__device__ int g_poffs[128];     // exclusive scan of partials

// FFMA-only exp: exp(x) = 2^(x*log2e). |x| small here, rel err ~2e-6.
__device__ __forceinline__ float fexp(float x) {
    float y = x * 1.44269504f;
    float r = rintf(y);
    float f = y - r;
    float p = 1.3333558e-3f;
    p = fmaf(p, f, 9.6181291e-3f);
    p = fmaf(p, f, 5.5504109e-2f);
    p = fmaf(p, f, 2.4022651e-1f);
    p = fmaf(p, f, 6.9314718e-1f);
    p = fmaf(p, f, 1.0f);
    return __int_as_float(__float_as_int(p) + ((int)r << 23));
}

__device__ __forceinline__ float leaky(float l) {
    return fmaxf(l, 0.f) + 0.2f * fminf(l, 0.f);
}

// -------- Kernel 1: per-node transform (thread per node, W in smem) --------
__global__ __launch_bounds__(NT) void node_kernel(const float* __restrict__ x,
                                                  const float* __restrict__ W,
                                                  const float* __restrict__ att_src,
                                                  const float* __restrict__ att_dst,
                                                  int N) {
    __shared__ __align__(16) float Ws[IN_F * HC];   // 8KB
    __shared__ __align__(16) float xs[NT * XPAD];
    __shared__ float s_att[2 * HC];

    int tid = threadIdx.x;
    int n0 = blockIdx.x * NT;
    int n = n0 + tid;

    if (n < N) g_cnt[n] = 0;   // zero counters for count_kernel

    {
        const float4* Wg = (const float4*)W;
        float4* Wsv = (float4*)Ws;
        for (int i = tid; i < IN_F * HC / 4; i += NT) Wsv[i] = Wg[i];
    }
    if (tid < HC) { s_att[tid] = att_src[tid]; s_att[HC + tid] = att_dst[tid]; }

    float acc[HC];
#pragma unroll
    for (int j = 0; j < HC; j++) acc[j] = 0.f;

#pragma unroll 1
    for (int kt = 0; kt < IN_F / KT; kt++) {
        __syncthreads();
        {
#pragma unroll
            for (int q = 0; q < KT / 4; q++) {   // 8 iters
                int idx = q * NT + tid;
                int r = idx >> 3, c = idx & 7;
                if (n0 + r < N) {
                    float4 v = *(const float4*)(x + (size_t)(n0 + r) * IN_F + kt * KT + c * 4);
                    *(float4*)&xs[r * XPAD + c * 4] = v;
                }
            }
        }
        __syncthreads();
        if (n < N) {
#pragma unroll
            for (int q = 0; q < KT / 4; q++) {
                float4 xv = *(const float4*)&xs[tid * XPAD + 4 * q];
                int kb = kt * KT + 4 * q;
                const float4* wr = (const float4*)&Ws[kb * HC];
#pragma unroll
                for (int kk = 0; kk < 4; kk++) {
                    float xk = (kk == 0) ? xv.x : (kk == 1) ? xv.y : (kk == 2) ? xv.z : xv.w;
                    float4 w0 = wr[kk * 4 + 0];
                    float4 w1 = wr[kk * 4 + 1];
                    float4 w2 = wr[kk * 4 + 2];
                    float4 w3 = wr[kk * 4 + 3];
                    acc[0]  = fmaf(xk, w0.x, acc[0]);
                    acc[1]  = fmaf(xk, w0.y, acc[1]);
                    acc[2]  = fmaf(xk, w0.z, acc[2]);
                    acc[3]  = fmaf(xk, w0.w, acc[3]);
                    acc[4]  = fmaf(xk, w1.x, acc[4]);
                    acc[5]  = fmaf(xk, w1.y, acc[5]);
                    acc[6]  = fmaf(xk, w1.z, acc[6]);
                    acc[7]  = fmaf(xk, w1.w, acc[7]);
                    acc[8]  = fmaf(xk, w2.x, acc[8]);
                    acc[9]  = fmaf(xk, w2.y, acc[9]);
                    acc[10] = fmaf(xk, w2.z, acc[10]);
                    acc[11] = fmaf(xk, w2.w, acc[11]);
                    acc[12] = fmaf(xk, w3.x, acc[12]);
                    acc[13] = fmaf(xk, w3.y, acc[13]);
                    acc[14] = fmaf(xk, w3.z, acc[14]);
                    acc[15] = fmaf(xk, w3.w, acc[15]);
                }
            }
        }
    }

    if (n >= N) return;

    // h in fp16 (32B row)
    {
        uint4 u0, u1;
        __half2 t;
        t = __floats2half2_rn(acc[0],  acc[1]);  u0.x = *(unsigned*)&t;
        t = __floats2half2_rn(acc[2],  acc[3]);  u0.y = *(unsigned*)&t;
        t = __floats2half2_rn(acc[4],  acc[5]);  u0.z = *(unsigned*)&t;
        t = __floats2half2_rn(acc[6],  acc[7]);  u0.w = *(unsigned*)&t;
        t = __floats2half2_rn(acc[8],  acc[9]);  u1.x = *(unsigned*)&t;
        t = __floats2half2_rn(acc[10], acc[11]); u1.y = *(unsigned*)&t;
        t = __floats2half2_rn(acc[12], acc[13]); u1.z = *(unsigned*)&t;
        t = __floats2half2_rn(acc[14], acc[15]); u1.w = *(unsigned*)&t;
        *(uint4*)(g_hh + (size_t)n * 8)     = u0;
        *(uint4*)(g_hh + (size_t)n * 8 + 4) = u1;
    }

    float as[HEADS], ad[HEADS];
#pragma unroll
    for (int hh = 0; hh < HEADS; hh++) {
        as[hh] = acc[2 * hh] * s_att[2 * hh] + acc[2 * hh + 1] * s_att[2 * hh + 1];
        ad[hh] = acc[2 * hh] * s_att[HC + 2 * hh] + acc[2 * hh + 1] * s_att[HC + 2 * hh + 1];
    }
    *(float4*)(g_asrc + (size_t)n * HEADS)     = make_float4(as[0], as[1], as[2], as[3]);
    *(float4*)(g_asrc + (size_t)n * HEADS + 4) = make_float4(as[4], as[5], as[6], as[7]);
    *(float4*)(g_adst + (size_t)n * HEADS)     = make_float4(ad[0], ad[1], ad[2], ad[3]);
    *(float4*)(g_adst + (size_t)n * HEADS + 4) = make_float4(ad[4], ad[5], ad[6], ad[7]);
}

// -------- Kernel 2: count in-degrees --------
__global__ __launch_bounds__(256) void count_kernel(const int* __restrict__ ei, int E) {
    int e = blockIdx.x * blockDim.x + threadIdx.x;
    if (e >= E) return;
    atomicAdd(&g_cnt[__ldg(&ei[E + e])], 1);   // compiles to RED (no return use)
}

// -------- Scan kernels: exclusive prefix sum of g_cnt into g_base --------
__global__ __launch_bounds__(1024) void scanA(int N) {
    __shared__ int sm[1024];
    int tid = threadIdx.x;
    int i = blockIdx.x * 1024 + tid;
    int v = (i < N) ? g_cnt[i] : 0;
    sm[tid] = v;
    __syncthreads();
#pragma unroll
    for (int off = 1; off < 1024; off <<= 1) {
        int t = (tid >= off) ? sm[tid - off] : 0;
        __syncthreads();
        sm[tid] += t;
        __syncthreads();
    }
    if (i < N) g_base[i] = sm[tid] - v;      // exclusive within block
    if (tid == 1023) g_partial[blockIdx.x] = sm[tid];
}

__global__ __launch_bounds__(128) void scanB(int nb) {
    __shared__ int sm[128];
    int tid = threadIdx.x;
    int v = (tid < nb) ? g_partial[tid] : 0;
    sm[tid] = v;
    __syncthreads();
#pragma unroll
    for (int off = 1; off < 128; off <<= 1) {
        int t = (tid >= off) ? sm[tid - off] : 0;
        __syncthreads();
        sm[tid] += t;
        __syncthreads();
    }
    g_poffs[tid] = sm[tid] - v;              // exclusive
}

__global__ __launch_bounds__(1024) void scanC(int N) {
    int i = blockIdx.x * 1024 + threadIdx.x;
    if (i >= N) return;
    int b = g_base[i] + g_poffs[blockIdx.x];
    g_base[i] = b;
    g_cursor[i] = b;
}

// -------- Kernel: scatter src ids grouped by dst --------
__global__ __launch_bounds__(256) void scatter_kernel(const int* __restrict__ ei, int E) {
    int e = blockIdx.x * blockDim.x + threadIdx.x;
    if (e >= E) return;
    int s = __ldg(&ei[e]);
    int d = __ldg(&ei[E + e]);
    int pos = atomicAdd(&g_cursor[d], 1);
    g_srcs[pos] = s;
}

// -------- Kernel: aggregate per dst + normalize + bias + FC (fused output) --------
// Warp per dst: lane = (slot = lane>>2) x (q = lane&3, head-pair). Self-loop is
// a virtual edge appended at index cnt. All accumulation in registers.
__global__ __launch_bounds__(256) void agg_kernel(const float* __restrict__ bias_gat,
                                                  const float* __restrict__ W_fc,
                                                  const float* __restrict__ b_fc,
                                                  float* __restrict__ out, int N) {
    int lane = threadIdx.x & 31;
    int dstN = blockIdx.x * 8 + (threadIdx.x >> 5);
    if (dstN >= N) return;
    int slot = lane >> 2;
    int q = lane & 3;

    int base = g_base[dstN];
    int cnt = g_cnt[dstN];
    float2 bv = *(const float2*)(g_adst + (size_t)dstN * HEADS + 2 * q);

    float S0 = 0.f, S1 = 0.f, S2 = 0.f, S3 = 0.f, Z0 = 0.f, Z1 = 0.f;
    int items = cnt + 1;   // + self-loop
    for (int it = slot; it < items; it += 8) {
        int s = (it < cnt) ? __ldg(&g_srcs[base + it]) : dstN;
        float2 a = *(const float2*)(g_asrc + (size_t)s * HEADS + 2 * q);
        float p0 = fexp(leaky(a.x + bv.x));
        float p1 = fexp(leaky(a.y + bv.y));
        uint2 hraw = *(const uint2*)(g_hh + (size_t)s * 8 + 2 * q);
        float2 f01 = __half22float2(*(__half2*)&hraw.x);
        float2 f23 = __half22float2(*(__half2*)&hraw.y);
        S0 = fmaf(p0, f01.x, S0);
        S1 = fmaf(p0, f01.y, S1);
        S2 = fmaf(p1, f23.x, S2);
        S3 = fmaf(p1, f23.y, S3);
        Z0 += p0;
        Z1 += p1;
    }

    // reduce across slots (all lanes end with per-q totals)
#pragma unroll
    for (int off = 4; off <= 16; off <<= 1) {
        S0 += __shfl_xor_sync(0xffffffffu, S0, off);
        S1 += __shfl_xor_sync(0xffffffffu, S1, off);
        S2 += __shfl_xor_sync(0xffffffffu, S2, off);
        S3 += __shfl_xor_sync(0xffffffffu, S3, off);
        Z0 += __shfl_xor_sync(0xffffffffu, Z0, off);
        Z1 += __shfl_xor_sync(0xffffffffu, Z1, off);
    }

    // normalize + bias, then FC partials for this q (values 4q..4q+3)
    float inv0 = 1.f / Z0, inv1 = 1.f / Z1;
    float g0 = fmaf(S0, inv0, __ldg(&bias_gat[4 * q + 0]));
    float g1 = fmaf(S1, inv0, __ldg(&bias_gat[4 * q + 1]));
    float g2 = fmaf(S2, inv1, __ldg(&bias_gat[4 * q + 2]));
    float g3 = fmaf(S3, inv1, __ldg(&bias_gat[4 * q + 3]));
    float o0 = g0 * __ldg(&W_fc[(4 * q + 0) * 2 + 0]) + g1 * __ldg(&W_fc[(4 * q + 1) * 2 + 0])
             + g2 * __ldg(&W_fc[(4 * q + 2) * 2 + 0]) + g3 * __ldg(&W_fc[(4 * q + 3) * 2 + 0]);
    float o1 = g0 * __ldg(&W_fc[(4 * q + 0) * 2 + 1]) + g1 * __ldg(&W_fc[(4 * q + 1) * 2 + 1])
             + g2 * __ldg(&W_fc[(4 * q + 2) * 2 + 1]) + g3 * __ldg(&W_fc[(4 * q + 3) * 2 + 1]);

    // reduce across q (lanes 0..3 within quad)
    o0 += __shfl_xor_sync(0xffffffffu, o0, 1);
    o1 += __shfl_xor_sync(0xffffffffu, o1, 1);
    o0 += __shfl_xor_sync(0xffffffffu, o0, 2);
    o1 += __shfl_xor_sync(0xffffffffu, o1, 2);

    if (lane == 0)
        ((float2*)out)[dstN] = make_float2(o0 + __ldg(&b_fc[0]), o1 + __ldg(&b_fc[1]));
}

extern "C" void kernel_launch(void* const* d_in, const int* in_sizes, int n_in,
                              void* d_out, int out_size) {
    const float* x        = (const float*)d_in[0];
    const int*   ei       = (const int*)d_in[1];   // int32 (JAX x64 disabled)
    // d_in[2] = edge_attr: unused (GATConv built without edge_dim)
    const float* W        = (const float*)d_in[3];
    const float* att_src  = (const float*)d_in[4];
    const float* att_dst  = (const float*)d_in[5];
    const float* bias_gat = (const float*)d_in[6];
    const float* W_fc     = (const float*)d_in[7];
    const float* b_fc     = (const float*)d_in[8];

    int N = in_sizes[0] / IN_F;
    int E = in_sizes[1] / 2;
    int nb = (N + 1023) / 1024;

    node_kernel<<<(N + NT - 1) / NT, NT>>>(x, W, att_src, att_dst, N);
    count_kernel<<<(E + 255) / 256, 256>>>(ei, E);
    scanA<<<nb, 1024>>>(N);
    scanB<<<1, 128>>>(nb);
    scanC<<<nb, 1024>>>(N);
    scatter_kernel<<<(E + 255) / 256, 256>>>(ei, E);
    agg_kernel<<<(N + 7) / 8, 256>>>(bias_gat, W_fc, b_fc, (float*)d_out, N);
}

// round 10
// speedup vs baseline: 1.1728x; 1.1728x over previous
#include <cuda_runtime.h>
#include <cuda_fp16.h>

#define IN_F   128
#define HEADS  8
#define HC     16   // HEADS * OUT_C
#define NMAX   100000
#define NT     128   // threads (=nodes) per CTA in node_kernel
#define KT     32    // k-tile width
#define XPAD   36    // padded row stride (floats)

// Static scratch (no allocations allowed)
__device__ __align__(128) __half2 g_hh[NMAX * 8];     // h in fp16: 32B per node row
__device__ __align__(128) float g_asrc[NMAX * HEADS]; // 32B per node row
__device__ __align__(128) float g_adst[NMAX * HEADS]; // 32B per node row
__device__ __align__(16)  float g_acc[NMAX * 24];     // per node: S[16] then Z[8]

// FFMA-only exp: exp(x) = 2^(x*log2e). |x| small here, rel err ~2e-6.
__device__ __forceinline__ float fexp(float x) {
    float y = x * 1.44269504f;
    float r = rintf(y);
    float f = y - r;
    float p = 1.3333558e-3f;
    p = fmaf(p, f, 9.6181291e-3f);
    p = fmaf(p, f, 5.5504109e-2f);
    p = fmaf(p, f, 2.4022651e-1f);
    p = fmaf(p, f, 6.9314718e-1f);
    p = fmaf(p, f, 1.0f);
    return __int_as_float(__float_as_int(p) + ((int)r << 23));
}

__device__ __forceinline__ float leaky(float l) {
    return fmaxf(l, 0.f) + 0.2f * fminf(l, 0.f);
}

// -------- Kernel 1: per-node transform + self-loop init --------
// Thread per node; W (8KB) in smem; x staged through smem in 32-col tiles,
// software-pipelined: next tile's LDGs are issued before computing the current
// tile so DRAM latency hides under the 128 FMAs.
__global__ __launch_bounds__(NT, 4) void node_kernel(const float* __restrict__ x,
                                                     const float* __restrict__ W,
                                                     const float* __restrict__ att_src,
                                                     const float* __restrict__ att_dst,
                                                     int N) {
    __shared__ __align__(16) float Ws[IN_F * HC];   // 8KB
    __shared__ __align__(16) float xs[NT * XPAD];   // 18.4KB
    __shared__ float s_att[2 * HC];

    int tid = threadIdx.x;
    int n0 = blockIdx.x * NT;
    int n = n0 + tid;

    {
        const float4* Wg = (const float4*)W;
        float4* Wsv = (float4*)Ws;
        for (int i = tid; i < IN_F * HC / 4; i += NT) Wsv[i] = Wg[i];
    }
    if (tid < HC) { s_att[tid] = att_src[tid]; s_att[HC + tid] = att_dst[tid]; }

    // Staging lane mapping: idx = q*NT + tid -> row r = idx>>3, col c = idx&7
    int valid = min(NT, N - n0);
    float4 stage[8];
    {
#pragma unroll
        for (int q = 0; q < 8; q++) {
            int idx = q * NT + tid;
            int r = idx >> 3, c = idx & 7;
            if (r < valid)
                stage[q] = *(const float4*)(x + (size_t)(n0 + r) * IN_F + 0 * KT + c * 4);
        }
    }

    float acc[HC];
#pragma unroll
    for (int j = 0; j < HC; j++) acc[j] = 0.f;

#pragma unroll 1
    for (int kt = 0; kt < IN_F / KT; kt++) {
        __syncthreads();   // previous tile's compute done reading xs
        {
#pragma unroll
            for (int q = 0; q < 8; q++) {
                int idx = q * NT + tid;
                int r = idx >> 3, c = idx & 7;
                if (r < valid) *(float4*)&xs[r * XPAD + c * 4] = stage[q];
            }
        }
        __syncthreads();   // tile visible
        // issue next tile's loads now; they fly during compute below
        if (kt < IN_F / KT - 1) {
#pragma unroll
            for (int q = 0; q < 8; q++) {
                int idx = q * NT + tid;
                int r = idx >> 3, c = idx & 7;
                if (r < valid)
                    stage[q] = *(const float4*)(x + (size_t)(n0 + r) * IN_F + (kt + 1) * KT + c * 4);
            }
        }
        if (n < N) {
#pragma unroll
            for (int q = 0; q < KT / 4; q++) {
                float4 xv = *(const float4*)&xs[tid * XPAD + 4 * q];
                int kb = kt * KT + 4 * q;
                const float4* wr = (const float4*)&Ws[kb * HC];
#pragma unroll
                for (int kk = 0; kk < 4; kk++) {
                    float xk = (kk == 0) ? xv.x : (kk == 1) ? xv.y : (kk == 2) ? xv.z : xv.w;
                    float4 w0 = wr[kk * 4 + 0];
                    float4 w1 = wr[kk * 4 + 1];
                    float4 w2 = wr[kk * 4 + 2];
                    float4 w3 = wr[kk * 4 + 3];
                    acc[0]  = fmaf(xk, w0.x, acc[0]);
                    acc[1]  = fmaf(xk, w0.y, acc[1]);
                    acc[2]  = fmaf(xk, w0.z, acc[2]);
                    acc[3]  = fmaf(xk, w0.w, acc[3]);
                    acc[4]  = fmaf(xk, w1.x, acc[4]);
                    acc[5]  = fmaf(xk, w1.y, acc[5]);
                    acc[6]  = fmaf(xk, w1.z, acc[6]);
                    acc[7]  = fmaf(xk, w1.w, acc[7]);
                    acc[8]  = fmaf(xk, w2.x, acc[8]);
                    acc[9]  = fmaf(xk, w2.y, acc[9]);
                    acc[10] = fmaf(xk, w2.z, acc[10]);
                    acc[11] = fmaf(xk, w2.w, acc[11]);
                    acc[12] = fmaf(xk, w3.x, acc[12]);
                    acc[13] = fmaf(xk, w3.y, acc[13]);
                    acc[14] = fmaf(xk, w3.z, acc[14]);
                    acc[15] = fmaf(xk, w3.w, acc[15]);
                }
            }
        }
    }

    if (n >= N) return;

    // h in fp16 (32B row)
    {
        uint4 u0, u1;
        __half2 t;
        t = __floats2half2_rn(acc[0],  acc[1]);  u0.x = *(unsigned*)&t;
        t = __floats2half2_rn(acc[2],  acc[3]);  u0.y = *(unsigned*)&t;
        t = __floats2half2_rn(acc[4],  acc[5]);  u0.z = *(unsigned*)&t;
        t = __floats2half2_rn(acc[6],  acc[7]);  u0.w = *(unsigned*)&t;
        t = __floats2half2_rn(acc[8],  acc[9]);  u1.x = *(unsigned*)&t;
        t = __floats2half2_rn(acc[10], acc[11]); u1.y = *(unsigned*)&t;
        t = __floats2half2_rn(acc[12], acc[13]); u1.z = *(unsigned*)&t;
        t = __floats2half2_rn(acc[14], acc[15]); u1.w = *(unsigned*)&t;
        *(uint4*)(g_hh + (size_t)n * 8)     = u0;
        *(uint4*)(g_hh + (size_t)n * 8 + 4) = u1;
    }

    float as[HEADS], ad[HEADS];
#pragma unroll
    for (int hh = 0; hh < HEADS; hh++) {
        as[hh] = acc[2 * hh] * s_att[2 * hh] + acc[2 * hh + 1] * s_att[2 * hh + 1];
        ad[hh] = acc[2 * hh] * s_att[HC + 2 * hh] + acc[2 * hh + 1] * s_att[HC + 2 * hh + 1];
    }
    *(float4*)(g_asrc + (size_t)n * HEADS)     = make_float4(as[0], as[1], as[2], as[3]);
    *(float4*)(g_asrc + (size_t)n * HEADS + 4) = make_float4(as[4], as[5], as[6], as[7]);
    *(float4*)(g_adst + (size_t)n * HEADS)     = make_float4(ad[0], ad[1], ad[2], ad[3]);
    *(float4*)(g_adst + (size_t)n * HEADS + 4) = make_float4(ad[4], ad[5], ad[6], ad[7]);

    float p[HEADS];
#pragma unroll
    for (int hh = 0; hh < HEADS; hh++) p[hh] = fexp(leaky(as[hh] + ad[hh]));

    float* accp = g_acc + (size_t)n * 24;
#pragma unroll
    for (int q = 0; q < 4; q++) {
        *(float4*)(accp + 4 * q) = make_float4(p[2 * q] * acc[4 * q],
                                               p[2 * q] * acc[4 * q + 1],
                                               p[2 * q + 1] * acc[4 * q + 2],
                                               p[2 * q + 1] * acc[4 * q + 3]);
    }
    *(float4*)(accp + 16) = make_float4(p[0], p[1], p[2], p[3]);
    *(float4*)(accp + 20) = make_float4(p[4], p[5], p[6], p[7]);
}

// -------- Kernel 2: per-edge gather + fast-exp + scatter (vector red) --------
// Four threads per edge: thread q in {0..3} handles heads 2q, 2q+1.
__global__ __launch_bounds__(256) void edge_kernel(const int* __restrict__ ei, int E) {
    int t = blockIdx.x * blockDim.x + threadIdx.x;
    int e = t >> 2;
    if (e >= E) return;
    int q = t & 3;
    int s = __ldg(&ei[e]);
    int d = __ldg(&ei[E + e]);

    float2 a = *(const float2*)(g_asrc + (size_t)s * HEADS + 2 * q);
    float2 b = *(const float2*)(g_adst + (size_t)d * HEADS + 2 * q);
    float p0 = fexp(leaky(a.x + b.x));
    float p1 = fexp(leaky(a.y + b.y));

    uint2 hraw = *(const uint2*)(g_hh + (size_t)s * 8 + 2 * q);
    float2 f01 = __half22float2(*(__half2*)&hraw.x);
    float2 f23 = __half22float2(*(__half2*)&hraw.y);

    float* accp = g_acc + (size_t)d * 24;
    asm volatile("red.global.add.v4.f32 [%0], {%1, %2, %3, %4};"
                 :: "l"(accp + 4 * q),
                    "f"(p0 * f01.x), "f"(p0 * f01.y),
                    "f"(p1 * f23.x), "f"(p1 * f23.y) : "memory");

    float pp0 = __shfl_xor_sync(0xffffffffu, p0, 1);
    float pp1 = __shfl_xor_sync(0xffffffffu, p1, 1);
    if ((q & 1) == 0) {
        asm volatile("red.global.add.v4.f32 [%0], {%1, %2, %3, %4};"
                     :: "l"(accp + 16 + 2 * q),
                        "f"(p0), "f"(p1), "f"(pp0), "f"(pp1) : "memory");
    }
}

// -------- Kernel 3: normalize + bias + FC --------
__global__ __launch_bounds__(256) void out_kernel(const float* __restrict__ bias_gat,
                                                  const float* __restrict__ W_fc,
                                                  const float* __restrict__ b_fc,
                                                  float* __restrict__ out, int N) {
    int n = blockIdx.x * blockDim.x + threadIdx.x;
    if (n >= N) return;
    const float4* ap = (const float4*)(g_acc + (size_t)n * 24);
    float4 s0 = ap[0], s1 = ap[1], s2 = ap[2], s3 = ap[3];
    float4 z0 = ap[4], z1 = ap[5];
    float S[16] = { s0.x, s0.y, s0.z, s0.w, s1.x, s1.y, s1.z, s1.w,
                    s2.x, s2.y, s2.z, s2.w, s3.x, s3.y, s3.z, s3.w };
    float Z[8]  = { z0.x, z0.y, z0.z, z0.w, z1.x, z1.y, z1.z, z1.w };

    float o0 = __ldg(&b_fc[0]), o1 = __ldg(&b_fc[1]);
#pragma unroll
    for (int hh = 0; hh < 8; hh++) {
        float inv = 1.f / Z[hh];   // Z >= exp(self-loop) > 0 always
        float g0 = S[2 * hh] * inv + __ldg(&bias_gat[2 * hh]);
        float g1 = S[2 * hh + 1] * inv + __ldg(&bias_gat[2 * hh + 1]);
        o0 += g0 * __ldg(&W_fc[(2 * hh) * 2 + 0]) + g1 * __ldg(&W_fc[(2 * hh + 1) * 2 + 0]);
        o1 += g0 * __ldg(&W_fc[(2 * hh) * 2 + 1]) + g1 * __ldg(&W_fc[(2 * hh + 1) * 2 + 1]);
    }
    ((float2*)out)[n] = make_float2(o0, o1);
}

extern "C" void kernel_launch(void* const* d_in, const int* in_sizes, int n_in,
                              void* d_out, int out_size) {
    const float* x        = (const float*)d_in[0];
    const int*   ei       = (const int*)d_in[1];   // int32 (JAX x64 disabled)
    // d_in[2] = edge_attr: unused (GATConv built without edge_dim)
    const float* W        = (const float*)d_in[3];
    const float* att_src  = (const float*)d_in[4];
    const float* att_dst  = (const float*)d_in[5];
    const float* bias_gat = (const float*)d_in[6];
    const float* W_fc     = (const float*)d_in[7];
    const float* b_fc     = (const float*)d_in[8];

    int N = in_sizes[0] / IN_F;
    int E = in_sizes[1] / 2;

    node_kernel<<<(N + NT - 1) / NT, NT>>>(x, W, att_src, att_dst, N);
    long long tthreads = 4LL * E;
    edge_kernel<<<(int)((tthreads + 255) / 256), 256>>>(ei, E);
    out_kernel<<<(N + 255) / 256, 256>>>(bias_gat, W_fc, b_fc, (float*)d_out, N);
}